// round 16
// baseline (speedup 1.0000x reference)
#include <cuda_runtime.h>
#include <cuda.h>
#include <cuda_fp16.h>
#include <cstdint>

// ---------------- problem constants ----------------
#define TT   8192
#define DD   1024
#define II   4096
#define EE   8
#define CAPACITY 2560
#define RR   (EE*CAPACITY)

// arch-specific (sm_103a/sm_100a) feature gate for tcgen05
#if defined(__CUDA_ARCH__) && (defined(__CUDA_ARCH_FEAT_SM103_ALL) || defined(__CUDA_ARCH_FEAT_SM100_ALL) || defined(__CUDA_ARCH_SPECIFIC__) || defined(__CUDA_ARCH_FAMILY_SPECIFIC__))
#define TC_PATH 1
#else
#define TC_PATH 0
#endif

// ---------------- device scratch ----------------
__device__ __half g_W1f[(size_t)EE*DD*II];
__device__ __half g_W2f[(size_t)EE*II*DD];
__device__ __half g_fw1f[(size_t)DD*II];
__device__ __half g_fw2f[(size_t)II*DD];
__device__ __half g_Xg [(size_t)RR*DD];
__device__ __half g_Xfb[(size_t)TT*DD];
__device__ __half g_H  [(size_t)RR*II];
__device__ __half g_Hfb[(size_t)TT*II];
__device__ __half g_Yeh [(size_t)RR*DD];
__device__ __half g_Yfbh[(size_t)TT*DD];
__device__ int    g_top2e[TT*2];
__device__ float  g_top2w[TT*2];
__device__ int    g_slot [TT*2];
__device__ int    g_fbslot[TT];
__device__ int    g_fbidx [TT];
__device__ unsigned char g_fbflag[TT];
__device__ int    g_counts[EE];
__device__ int    g_fbcount;
__device__ int    g_idx[RR];

// ---------------- generic helpers ----------------
__device__ __forceinline__ float gelu_exact(float v) {
    return 0.5f * v * (1.0f + erff(v * 0.7071067811865475f));
}
__device__ __forceinline__ void cpasync16(uint32_t dst, const void* src) {
    asm volatile("cp.async.cg.shared.global [%0], [%1], 16;\n" :: "r"(dst), "l"(src));
}
__device__ __forceinline__ void cpasync_commit() { asm volatile("cp.async.commit_group;\n"); }
__device__ __forceinline__ void cpasync_wait0() { asm volatile("cp.async.wait_group 0;\n"); }
__device__ __forceinline__ void cpasync_wait1() { asm volatile("cp.async.wait_group 1;\n"); }

__device__ __forceinline__ uint32_t smem_u32(const void* p) {
    uint32_t a;
    asm("{ .reg .u64 t; cvta.to.shared.u64 t, %1; cvt.u32.u64 %0, t; }" : "=r"(a) : "l"(p));
    return a;
}
__device__ __forceinline__ void ldmatrix_x4(uint32_t* r, uint32_t addr) {
    asm volatile("ldmatrix.sync.aligned.m8n8.x4.shared.b16 {%0,%1,%2,%3}, [%4];"
                 : "=r"(r[0]), "=r"(r[1]), "=r"(r[2]), "=r"(r[3]) : "r"(addr));
}
__device__ __forceinline__ void ldmatrix_x4_trans(uint32_t* r, uint32_t addr) {
    asm volatile("ldmatrix.sync.aligned.m8n8.x4.trans.shared.b16 {%0,%1,%2,%3}, [%4];"
                 : "=r"(r[0]), "=r"(r[1]), "=r"(r[2]), "=r"(r[3]) : "r"(addr));
}
__device__ __forceinline__ void mma16816(float* c, const uint32_t* a, const uint32_t* b) {
    asm volatile("mma.sync.aligned.m16n8k16.row.col.f32.f16.f16.f32 "
                 "{%0,%1,%2,%3},{%4,%5,%6,%7},{%8,%9},{%0,%1,%2,%3};"
                 : "+f"(c[0]), "+f"(c[1]), "+f"(c[2]), "+f"(c[3])
                 : "r"(a[0]), "r"(a[1]), "r"(a[2]), "r"(a[3]), "r"(b[0]), "r"(b[1]));
}

// ---------------- mbarrier helpers ----------------
__device__ __forceinline__ void mbar_init(uint32_t a, uint32_t cnt) {
    asm volatile("mbarrier.init.shared.b64 [%0], %1;" :: "r"(a), "r"(cnt) : "memory");
}
__device__ __forceinline__ void mbar_arrive(uint32_t a) {
    asm volatile("mbarrier.arrive.shared.b64 _, [%0];" :: "r"(a) : "memory");
}
__device__ __forceinline__ void mbar_expect_tx(uint32_t a, uint32_t bytes) {
    asm volatile("mbarrier.arrive.expect_tx.shared.b64 _, [%0], %1;" :: "r"(a), "r"(bytes) : "memory");
}
__device__ __forceinline__ void mbar_wait(uint32_t a, uint32_t parity) {
    asm volatile(
        "{\n\t"
        ".reg .pred P1;\n\t"
        "WAIT_LOOP_%=:\n\t"
        "mbarrier.try_wait.parity.acquire.cta.shared::cta.b64 P1, [%0], %1, 0x989680;\n\t"
        "@P1 bra.uni WAIT_DONE_%=;\n\t"
        "bra.uni WAIT_LOOP_%=;\n\t"
        "WAIT_DONE_%=:\n\t"
        "}"
        :: "r"(a), "r"(parity) : "memory");
}
__device__ __forceinline__ void fence_proxy_async_shared() {
    asm volatile("fence.proxy.async.shared::cta;" ::: "memory");
}
// 2D TMA load global->shared::cta, mbarrier complete_tx
__device__ __forceinline__ void tma2d(uint32_t smemaddr, const CUtensorMap* tm,
                                      int cx, int cy, uint32_t mbar) {
    asm volatile("cp.async.bulk.tensor.2d.shared::cta.global.tile.mbarrier::complete_tx::bytes "
                 "[%0], [%1, {%2, %3}], [%4];"
                 :: "r"(smemaddr), "l"(tm), "r"(cx), "r"(cy), "r"(mbar) : "memory");
}

// ---------------- fp32 -> fp16 plain convert (HMMA layout [K,N]) ----------------
__global__ void convert_kernel(const float* __restrict__ src, __half* __restrict__ dst, int n8) {
    int i = blockIdx.x * blockDim.x + threadIdx.x;
    if (i < n8) {
        float4 a = reinterpret_cast<const float4*>(src)[2*i];
        float4 b = reinterpret_cast<const float4*>(src)[2*i+1];
        union { __half2 h[4]; uint4 u; } o;
        o.h[0] = __floats2half2_rn(a.x, a.y);
        o.h[1] = __floats2half2_rn(a.z, a.w);
        o.h[2] = __floats2half2_rn(b.x, b.y);
        o.h[3] = __floats2half2_rn(b.z, b.w);
        reinterpret_cast<uint4*>(dst)[i] = o.u;
    }
}

// ---------------- transpose-convert tile body (TC layout [N,K]) ----------------
__device__ __forceinline__ void tconv_tile(const float* __restrict__ src, __half* __restrict__ dst,
                                           int Kdim, int Ndim, int kb, int nb,
                                           float (*tile)[65], int tid) {
    #pragma unroll
    for (int p = 0; p < 4; p++) {
        int i = p * 256 + tid;
        int r = i >> 4, c4 = i & 15;
        float4 v = *reinterpret_cast<const float4*>(src + (size_t)(kb + r) * Ndim + nb + c4 * 4);
        tile[r][c4*4+0] = v.x; tile[r][c4*4+1] = v.y;
        tile[r][c4*4+2] = v.z; tile[r][c4*4+3] = v.w;
    }
    __syncthreads();
    #pragma unroll
    for (int p = 0; p < 2; p++) {
        int i = p * 256 + tid;
        int r = i >> 3, c = i & 7;
        union { __half2 h[4]; uint4 u; } o;
        #pragma unroll
        for (int j = 0; j < 4; j++)
            o.h[j] = __floats2half2_rn(tile[c*8 + 2*j][r], tile[c*8 + 2*j + 1][r]);
        *reinterpret_cast<uint4*>(dst + (size_t)(nb + r) * Kdim + kb + c * 8) = o.u;
    }
}

// ---------------- router ----------------
__global__ void router_kernel(const float* __restrict__ x, const float* __restrict__ Wr) {
    __shared__ float sWr[EE*DD];
    int tid = threadIdx.x;
    for (int i = tid; i < EE*DD; i += 256) sWr[i] = Wr[i];
    __syncthreads();
    int w = tid >> 5, lane = tid & 31;
    int t = blockIdx.x * 8 + w;
    const float* xr = x + (size_t)t * DD;
    float acc[EE];
    #pragma unroll
    for (int e = 0; e < EE; e++) acc[e] = 0.f;
    for (int d = lane; d < DD; d += 32) {
        float xv = xr[d];
        #pragma unroll
        for (int e = 0; e < EE; e++) acc[e] += xv * sWr[e*DD + d];
    }
    #pragma unroll
    for (int e = 0; e < EE; e++)
        #pragma unroll
        for (int o = 16; o > 0; o >>= 1) acc[e] += __shfl_xor_sync(0xffffffffu, acc[e], o);
    if (lane == 0) {
        float m = acc[0];
        #pragma unroll
        for (int e = 1; e < EE; e++) m = fmaxf(m, acc[e]);
        float p[EE], s = 0.f;
        #pragma unroll
        for (int e = 0; e < EE; e++) { p[e] = expf(acc[e] - m); s += p[e]; }
        #pragma unroll
        for (int e = 0; e < EE; e++) p[e] /= s;
        int i1 = 0;
        #pragma unroll
        for (int e = 1; e < EE; e++) if (p[e] > p[i1]) i1 = e;
        int i2 = -1;
        #pragma unroll
        for (int e = 0; e < EE; e++) if (e != i1 && (i2 < 0 || p[e] > p[i2])) i2 = e;
        float ssum = p[i1] + p[i2];
        if (ssum < 1e-9f) ssum = 1e-9f;
        g_top2e[2*t] = i1; g_top2e[2*t+1] = i2;
        g_top2w[2*t] = p[i1] / ssum; g_top2w[2*t+1] = p[i2] / ssum;
    }
}

// ---------------- sequential capacity assignment ----------------
__global__ void assign_kernel() {
    int tid = threadIdx.x, lane = tid & 31, wid = tid >> 5;
    __shared__ int wsum[32];
    int e0[8], e1[8];
    bool fb[8];
    #pragma unroll
    for (int i = 0; i < 8; i++) {
        int t = tid * 8 + i;
        e0[i] = g_top2e[2*t]; e1[i] = g_top2e[2*t+1];
        fb[i] = false;
    }
    for (int e = 0; e < EE; e++) {
        bool elig[8]; int cnt = 0;
        #pragma unroll
        for (int i = 0; i < 8; i++) {
            elig[i] = (!fb[i]) && (e0[i] == e || e1[i] == e);
            cnt += elig[i] ? 1 : 0;
        }
        int inc = cnt;
        #pragma unroll
        for (int o = 1; o < 32; o <<= 1) { int v = __shfl_up_sync(0xffffffffu, inc, o); if (lane >= o) inc += v; }
        if (lane == 31) wsum[wid] = inc;
        __syncthreads();
        if (wid == 0) {
            int v = wsum[lane];
            int inc2 = v;
            #pragma unroll
            for (int o = 1; o < 32; o <<= 1) { int u = __shfl_up_sync(0xffffffffu, inc2, o); if (lane >= o) inc2 += u; }
            wsum[lane] = inc2;
        }
        __syncthreads();
        int pos = inc - cnt + (wid ? wsum[wid-1] : 0);
        int total = wsum[31];
        if (tid == 0) g_counts[e] = (total < CAPACITY) ? total : CAPACITY;
        #pragma unroll
        for (int i = 0; i < 8; i++) {
            if (elig[i]) {
                int t = tid * 8 + i;
                if (pos < CAPACITY) {
                    int k = (e0[i] == e) ? 0 : 1;
                    g_slot[2*t + k] = pos;
                    g_idx[e*CAPACITY + pos] = t;
                } else {
                    fb[i] = true;
                }
                pos++;
            }
        }
        __syncthreads();
    }
    int cnt = 0;
    #pragma unroll
    for (int i = 0; i < 8; i++) cnt += fb[i] ? 1 : 0;
    int inc = cnt;
    #pragma unroll
    for (int o = 1; o < 32; o <<= 1) { int v = __shfl_up_sync(0xffffffffu, inc, o); if (lane >= o) inc += v; }
    if (lane == 31) wsum[wid] = inc;
    __syncthreads();
    if (wid == 0) {
        int v = wsum[lane];
        int inc2 = v;
        #pragma unroll
        for (int o = 1; o < 32; o <<= 1) { int u = __shfl_up_sync(0xffffffffu, inc2, o); if (lane >= o) inc2 += u; }
        wsum[lane] = inc2;
    }
    __syncthreads();
    int pos = inc - cnt + (wid ? wsum[wid-1] : 0);
    #pragma unroll
    for (int i = 0; i < 8; i++) {
        int t = tid * 8 + i;
        g_fbflag[t] = fb[i] ? 1 : 0;
        if (fb[i]) { g_fbidx[pos] = t; g_fbslot[t] = pos; pos++; }
    }
    if (tid == 0) g_fbcount = wsum[31];
}

// ---------------- gather body ----------------
__device__ __forceinline__ void gather_body(const float* __restrict__ x, int r, int i) {
    int t;
    __half* dstrow;
    if (r < RR) {
        int e = r / CAPACITY;
        if (r - e*CAPACITY >= g_counts[e]) return;
        t = g_idx[r];
        dstrow = g_Xg + (size_t)r * DD;
    } else {
        int rr = r - RR;
        if (rr >= g_fbcount) return;
        t = g_fbidx[rr];
        dstrow = g_Xfb + (size_t)rr * DD;
    }
    const float4* src = reinterpret_cast<const float4*>(x + (size_t)t * DD);
    __half2* dst = reinterpret_cast<__half2*>(dstrow);
    float4 v = src[i];
    dst[2*i]   = __floats2half2_rn(v.x, v.y);
    dst[2*i+1] = __floats2half2_rn(v.z, v.w);
}

__global__ void gather_all(const float* __restrict__ x) {
    gather_body(x, blockIdx.x, threadIdx.x);
}

// ---------------- mega-prep ----------------
#define MP_GATHER (RR + TT)
#define MP_W1     (16*64*EE)
#define MP_W2     (64*16*EE)
#define MP_FW1    (16*64)
#define MP_FW2    (64*16)
#define MP_TOTAL  (MP_GATHER + MP_W1 + MP_W2 + MP_FW1 + MP_FW2)

__global__ void megaprep(const float* __restrict__ x,
                         const float* __restrict__ W1, const float* __restrict__ W2,
                         const float* __restrict__ fw1, const float* __restrict__ fw2) {
    __shared__ float tile[64][65];
    int b = blockIdx.x, tid = threadIdx.x;
    if (b < MP_GATHER) { gather_body(x, b, tid); return; }
    b -= MP_GATHER;
    if (b < MP_W1) {
        int kb = (b & 15) * 64;
        int t2 = b >> 4;
        int nb = (t2 & 63) * 64;
        int z  = t2 >> 6;
        tconv_tile(W1 + (size_t)z*DD*II, g_W1f + (size_t)z*DD*II, DD, II, kb, nb, tile, tid);
        return;
    }
    b -= MP_W1;
    if (b < MP_W2) {
        int kb = (b & 63) * 64;
        int t2 = b >> 6;
        int nb = (t2 & 15) * 64;
        int z  = t2 >> 4;
        tconv_tile(W2 + (size_t)z*II*DD, g_W2f + (size_t)z*II*DD, II, DD, kb, nb, tile, tid);
        return;
    }
    b -= MP_W2;
    if (b < MP_FW1) {
        int kb = (b & 15) * 64;
        int nb = (b >> 4) * 64;
        tconv_tile(fw1, g_fw1f, DD, II, kb, nb, tile, tid);
        return;
    }
    b -= MP_FW1;
    {
        int kb = (b & 63) * 64;
        int nb = (b >> 6) * 64;
        tconv_tile(fw2, g_fw2f, II, DD, kb, nb, tile, tid);
    }
}

// ============================================================================
// Path A: tcgen05 GEMM, M=128/CTA, NSTG=2, cluster (1,2,1) with B multicast
// ============================================================================
#define TCBM 128
#define TCBN 256
#define BKH 64
#define NSTG 2
#define TC_A1 16384
#define TC_STGB 49152
#define SM_TILE0 2048
#define TC_SMEM (SM_TILE0 + NSTG*TC_STGB)   // 100352 -> 2 CTAs/SM

#define IDESC_F16_128x256 ((1u<<4) | (32u<<17) | (8u<<24))

#if TC_PATH
static __device__ __forceinline__ uint64_t make_desc(uint32_t addr) {
    const uint64_t base =
        (uint64_t(2)  << 61) | (uint64_t(1) << 46) | (uint64_t(64) << 32) | (uint64_t(1) << 16);
    return base | ((uint64_t)(addr >> 4) & 0x3FFF);
}
__device__ __forceinline__ void mma_f16_ss(uint32_t d_tmem, uint64_t adesc, uint64_t bdesc,
                                           uint32_t idesc, bool accum) {
    uint32_t en = accum ? 1u : 0u;
    asm volatile(
        "{\n\t"
        ".reg .pred p;\n\t"
        "setp.ne.u32 p, %5, 0;\n\t"
        "tcgen05.mma.cta_group::1.kind::f16 [%0], %1, %2, %3, {%4, %4, %4, %4}, p;\n\t"
        "}"
        :: "r"(d_tmem), "l"(adesc), "l"(bdesc), "r"(idesc), "r"(0u), "r"(en)
        : "memory");
}
#define TC_LD32(r, addr) \
    asm volatile( \
        "tcgen05.ld.sync.aligned.32x32b.x32.b32 " \
        "{%0, %1, %2, %3, %4, %5, %6, %7, " \
        " %8, %9, %10, %11, %12, %13, %14, %15, " \
        " %16, %17, %18, %19, %20, %21, %22, %23, " \
        " %24, %25, %26, %27, %28, %29, %30, %31}, [%32];" \
        : "=r"((r)[0]),  "=r"((r)[1]),  "=r"((r)[2]),  "=r"((r)[3]), \
          "=r"((r)[4]),  "=r"((r)[5]),  "=r"((r)[6]),  "=r"((r)[7]), \
          "=r"((r)[8]),  "=r"((r)[9]),  "=r"((r)[10]), "=r"((r)[11]), \
          "=r"((r)[12]), "=r"((r)[13]), "=r"((r)[14]), "=r"((r)[15]), \
          "=r"((r)[16]), "=r"((r)[17]), "=r"((r)[18]), "=r"((r)[19]), \
          "=r"((r)[20]), "=r"((r)[21]), "=r"((r)[22]), "=r"((r)[23]), \
          "=r"((r)[24]), "=r"((r)[25]), "=r"((r)[26]), "=r"((r)[27]), \
          "=r"((r)[28]), "=r"((r)[29]), "=r"((r)[30]), "=r"((r)[31]) \
        : "r"(addr))
__device__ __forceinline__ uint32_t cluster_rank() {
    uint32_t r; asm("mov.u32 %0, %%cluster_ctarank;" : "=r"(r)); return r;
}
#endif

template<int PHASE>
__global__ void __launch_bounds__(256, 2) gemm_tc5(
    const __grid_constant__ CUtensorMap tmAe,
    const __grid_constant__ CUtensorMap tmAf,
    const __grid_constant__ CUtensorMap tmBe,
    const __grid_constant__ CUtensorMap tmBf,
    const float* __restrict__ bias_e,
    const float* __restrict__ bias_f) {
#if TC_PATH
    constexpr bool G1 = (PHASE == 1);
    constexpr int N = G1 ? II : DD;
    constexpr int KT = (G1 ? DD : II) / BKH;

    const int z = blockIdx.z;
    const bool FB = (z == EE);
    const int count = FB ? g_fbcount : g_counts[z];
    const int m0 = blockIdx.y * TCBM;
    const int pm0 = (int)(blockIdx.y & ~1u) * TCBM;   // pair leader's m0
    if (pm0 >= count) return;                          // whole pair inactive
    const bool active = (m0 < count);                  // ghost keeps pipeline, skips stores
    const uint32_t rank = cluster_rank();

    const CUtensorMap* tmA = FB ? &tmAf : &tmAe;
    const CUtensorMap* tmB = FB ? &tmBf : &tmBe;
    const int n0 = blockIdx.x * TCBN;
    const int rowA = FB ? m0 : z*CAPACITY + m0;
    const int rowB = FB ? n0 : z*N + n0;
    const float* biasp = FB ? bias_f : bias_e + (size_t)z*N;

    extern __shared__ char smem[];
    const uint32_t sb = smem_u32(smem);
    const int tid = threadIdx.x, lane = tid & 31, wid = tid >> 5;

    const uint32_t mb_full0 = sb + 64, mb_empty0 = sb + 96, mb_done = sb + 120;
    const uint32_t mb_bready0 = sb + 128;   // 2 stages x 8B, count=2
    float* bias_sm = reinterpret_cast<float*>(smem + 1024);
    if (tid == 0) {
        #pragma unroll
        for (int s = 0; s < NSTG; s++) {
            mbar_init(mb_full0 + 8*s, 1);
            mbar_init(mb_empty0 + 8*s, 1);
            mbar_init(mb_bready0 + 8*s, 2);
        }
        mbar_init(mb_done, 1);
    }
    bias_sm[tid] = biasp[n0 + tid];
    if (wid == 0) {
        asm volatile("tcgen05.alloc.cta_group::1.sync.aligned.shared::cta.b32 [%0], %1;"
                     :: "r"(sb), "r"(256) : "memory");
        asm volatile("tcgen05.relinquish_alloc_permit.cta_group::1.sync.aligned;");
    }
    __syncthreads();
    // both CTAs' barriers initialized before any cluster arrival / multicast
    asm volatile("barrier.cluster.arrive.aligned;" ::: "memory");
    asm volatile("barrier.cluster.wait.aligned;" ::: "memory");
    uint32_t tb;
    asm volatile("ld.shared.b32 %0, [%1];" : "=r"(tb) : "r"(sb));

    if (wid == 0 && lane == 0) {
        // MMA issuer
        uint64_t ad[NSTG], bd[NSTG];
        #pragma unroll
        for (int s = 0; s < NSTG; s++) {
            uint32_t base = sb + SM_TILE0 + s*TC_STGB;
            ad[s] = make_desc(base);
            bd[s] = make_desc(base + TC_A1);
        }
        #pragma unroll 1
        for (int kt = 0; kt < KT; kt++) {
            int st = kt & 1;
            uint32_t ph = (kt >> 1) & 1;
            mbar_wait(mb_full0 + 8*st, ph);
            asm volatile("tcgen05.fence::after_thread_sync;" ::: "memory");
            #pragma unroll
            for (int k = 0; k < 4; k++)
                mma_f16_ss(tb, ad[st] + k*2, bd[st] + k*2, IDESC_F16_128x256, (kt > 0) || (k > 0));
            asm volatile("tcgen05.commit.cta_group::1.mbarrier::arrive::one.shared::cluster.b64 [%0];"
                         :: "r"(mb_empty0 + 8*st) : "memory");
        }
        asm volatile("tcgen05.commit.cta_group::1.mbarrier::arrive::one.shared::cluster.b64 [%0];"
                     :: "r"(mb_done) : "memory");
    } else if (tid == 32) {
        // A producer + B-ready signaler (both CTAs of the pair)
        #pragma unroll 1
        for (int kt = 0; kt < KT; kt++) {
            int st = kt & 1;
            uint32_t eph = ((kt >> 1) & 1) ^ 1u;
            mbar_wait(mb_empty0 + 8*st, eph);
            uint32_t fullb = mb_full0 + 8*st;
            mbar_expect_tx(fullb, (uint32_t)TC_STGB);   // A 16K + B 32K
            tma2d(sb + SM_TILE0 + st*TC_STGB, tmA, kt*BKH, rowA, fullb);
            // arrive on rank0's bready[st]: "my expect for stage st is set"
            asm volatile(
                "{ .reg .b32 ra; mapa.shared::cluster.u32 ra, %0, 0; "
                "mbarrier.arrive.shared::cluster.b64 _, [ra]; }"
                :: "r"(mb_bready0 + 8*st) : "memory");
        }
    } else if (rank == 0 && tid == 64) {
        // B multicast issuer: one load per stage serves both CTAs of the pair
        #pragma unroll 1
        for (int kt = 0; kt < KT; kt++) {
            int st = kt & 1;
            uint32_t ph = (kt >> 1) & 1;
            mbar_wait(mb_bready0 + 8*st, ph);
            asm volatile(
                "cp.async.bulk.tensor.2d.shared::cluster.global.tile"
                ".mbarrier::complete_tx::bytes.multicast::cluster "
                "[%0], [%1, {%2, %3}], [%4], %5;"
                :: "r"(sb + SM_TILE0 + st*TC_STGB + TC_A1), "l"(tmB),
                   "r"(kt*BKH), "r"(rowB), "r"(mb_full0 + 8*st), "h"((uint16_t)0x3)
                : "memory");
        }
    }

    mbar_wait(mb_done, 0);
    asm volatile("tcgen05.fence::after_thread_sync;" ::: "memory");

    if (active) {
        const int ch = wid >> 2;
        const int lw = wid & 3;
        const int row = m0 + lw*32 + lane;
        const uint32_t cbase = (uint32_t)ch * 128;
        __half* outp;
        if constexpr (G1)
            outp = (FB ? g_Hfb : g_H + (size_t)z*CAPACITY*II) + (size_t)row * II;
        else
            outp = (FB ? g_Yfbh : g_Yeh + (size_t)z*CAPACITY*DD) + (size_t)row * DD;
        uint32_t ra[32], rb[32];
        #pragma unroll 1
        for (int cc = 0; cc < 2; cc++) {
            TC_LD32(ra, tb + cbase + (2*cc)*32);
            TC_LD32(rb, tb + cbase + (2*cc+1)*32);
            asm volatile("tcgen05.wait::ld.sync.aligned;" ::: "memory");
            #pragma unroll
            for (int half = 0; half < 2; half++) {
                const uint32_t* r = half ? rb : ra;
                int cl = cbase + (2*cc + half)*32;
                union { __half2 h[16]; uint4 u[4]; } o;
                #pragma unroll
                for (int j = 0; j < 16; j++) {
                    float v0 = __uint_as_float(r[2*j])   + bias_sm[cl + 2*j];
                    float v1 = __uint_as_float(r[2*j+1]) + bias_sm[cl + 2*j + 1];
                    if constexpr (G1) { v0 = gelu_exact(v0); v1 = gelu_exact(v1); }
                    o.h[j] = __floats2half2_rn(v0, v1);
                }
                uint4* dst = reinterpret_cast<uint4*>(outp + n0 + cl);
                dst[0] = o.u[0]; dst[1] = o.u[1]; dst[2] = o.u[2]; dst[3] = o.u[3];
            }
        }
    }
    __syncthreads();
    if (wid == 0) {
        asm volatile("tcgen05.dealloc.cta_group::1.sync.aligned.b32 %0, %1;" :: "r"(tb), "r"(256));
    }
    asm volatile("barrier.cluster.arrive.aligned;" ::: "memory");
    asm volatile("barrier.cluster.wait.aligned;" ::: "memory");
#endif
}

// ============================================================================
// Path B: HMMA GEMM fallback ([K,N] weights), 128x128 tiles, 3-stage
// ============================================================================
#define BM 128
#define BN 128
#define HM_STGB 32768
#define HM_SMEM (3*HM_STGB)

template<int MODE>
__global__ void gemm_hmma(const float* __restrict__ bias) {
    constexpr bool G1 = (MODE < 2);
    constexpr bool FB = (MODE & 1);
    constexpr int K = G1 ? DD : II;
    constexpr int N = G1 ? II : DD;
    constexpr int KT = K / BKH;

    const int e = blockIdx.z;
    const int count = FB ? g_fbcount : g_counts[e];
    const int m0 = blockIdx.y * BM;
    if (m0 >= count) return;
    const int n0 = blockIdx.x * BN;

    const __half* __restrict__ Aexp;
    const __half* __restrict__ Bexp;
    if constexpr (MODE == 0) { Aexp = g_Xg  + (size_t)e*CAPACITY*K; Bexp = g_W1f + (size_t)e*K*II; }
    if constexpr (MODE == 1) { Aexp = g_Xfb;                        Bexp = g_fw1f; }
    if constexpr (MODE == 2) { Aexp = g_H   + (size_t)e*CAPACITY*K; Bexp = g_W2f + (size_t)e*K*DD; }
    if constexpr (MODE == 3) { Aexp = g_Hfb;                        Bexp = g_fw2f; }
    const float* biasp = bias + (FB ? 0 : (size_t)e*N);

    extern __shared__ __half smemh[];
    const uint32_t sbase = smem_u32(smemh);
    const int tid = threadIdx.x, lane = tid & 31, wid = tid >> 5;
    const int wm = wid & 1, wn = wid >> 1;
    const int g = lane >> 3, rin = lane & 7;

    float acc[4][4][4];
    #pragma unroll
    for (int a = 0; a < 4; a++)
        #pragma unroll
        for (int b = 0; b < 4; b++)
            #pragma unroll
            for (int c = 0; c < 4; c++) acc[a][b][c] = 0.f;

    auto loadStage = [&](int kt, int st) {
        if (kt < KT) {
            uint32_t aB = sbase + st * HM_STGB;
            uint32_t bB = aB + 16384;
            #pragma unroll
            for (int j = 0; j < 4; j++) {
                int id = j * 256 + tid;
                int r = id >> 3, c = id & 7;
                const __half* src = Aexp + (size_t)(m0 + r) * K + kt * BKH + c * 8;
                uint32_t dst = aB + (uint32_t)(r * 64 + ((c ^ (r & 7)) << 3)) * 2;
                cpasync16(dst, src);
            }
            #pragma unroll
            for (int j = 0; j < 4; j++) {
                int id = j * 256 + tid;
                int r = id >> 4, c = id & 15;
                const __half* src = Bexp + (size_t)(kt * BKH + r) * N + n0 + c * 8;
                uint32_t dst = bB + (uint32_t)(r * 128 + (((c & 8) | ((c ^ r) & 7)) << 3)) * 2;
                cpasync16(dst, src);
            }
        }
        cpasync_commit();
    };

    loadStage(0, 0);
    loadStage(1, 1);
    int st = 0;
    #pragma unroll 1
    for (int kt = 0; kt < KT; kt++) {
        cpasync_wait1();
        __syncthreads();
        loadStage(kt + 2, (st + 2) % 3);
        uint32_t aB = sbase + st * HM_STGB;
        uint32_t bB = aB + 16384;
        #pragma unroll
        for (int ks = 0; ks < 4; ks++) {
            uint32_t afr[4][4];
            #pragma unroll
            for (int mt = 0; mt < 4; mt++) {
                int row = wm * 64 + mt * 16 + (g & 1) * 8 + rin;
                int ch = (ks * 2 + (g >> 1)) ^ rin;
                ldmatrix_x4(afr[mt], aB + (uint32_t)(row * 64 + ch * 8) * 2);
            }
            uint32_t bfr[4][2];
            #pragma unroll
            for (int ht = 0; ht < 2; ht++) {
                int row = ks * 16 + (g & 1) * 8 + rin;
                int c = wn * 4 + ht * 2 + (g >> 1);
                int ph = (c & 8) | ((c & 7) ^ rin);
                uint32_t r4[4];
                ldmatrix_x4_trans(r4, bB + (uint32_t)(row * 128 + ph * 8) * 2);
                bfr[ht*2][0] = r4[0]; bfr[ht*2][1] = r4[1];
                bfr[ht*2+1][0] = r4[2]; bfr[ht*2+1][1] = r4[3];
            }
            #pragma unroll
            for (int mt = 0; mt < 4; mt++)
                #pragma unroll
                for (int nt = 0; nt < 4; nt++)
                    mma16816(acc[mt][nt], afr[mt], bfr[nt]);
        }
        st = (st + 1) % 3;
    }

    const int growb = m0 + wm * 64;
    const int gcolb = n0 + wn * 32;
    #pragma unroll
    for (int mt = 0; mt < 4; mt++) {
        #pragma unroll
        for (int nt = 0; nt < 4; nt++) {
            int r0 = growb + mt * 16 + (lane >> 2);
            int c0 = gcolb + nt * 8 + (lane & 3) * 2;
            float b0f = biasp[c0], b1f = biasp[c0 + 1];
            float x0 = acc[mt][nt][0] + b0f, x1 = acc[mt][nt][1] + b1f;
            float x2 = acc[mt][nt][2] + b0f, x3 = acc[mt][nt][3] + b1f;
            if constexpr (G1) {
                __half* Hout = FB ? g_Hfb : (g_H + (size_t)e*CAPACITY*N);
                *reinterpret_cast<__half2*>(Hout + (size_t)r0 * N + c0) =
                    __floats2half2_rn(gelu_exact(x0), gelu_exact(x1));
                *reinterpret_cast<__half2*>(Hout + (size_t)(r0 + 8) * N + c0) =
                    __floats2half2_rn(gelu_exact(x2), gelu_exact(x3));
            } else {
                __half* Yout = FB ? g_Yfbh : (g_Yeh + (size_t)e*CAPACITY*N);
                *reinterpret_cast<__half2*>(Yout + (size_t)r0 * N + c0) =
                    __floats2half2_rn(x0, x1);
                *reinterpret_cast<__half2*>(Yout + (size_t)(r0 + 8) * N + c0) =
                    __floats2half2_rn(x2, x3);
            }
        }
    }
}

// ---------------- final combine (fp16 expert outputs) ----------------
__global__ void combine_kernel(float* __restrict__ out) {
    int t = blockIdx.x;
    int i = threadIdx.x;
    float4* o = reinterpret_cast<float4*>(out + (size_t)t * DD);
    if (g_fbflag[t]) {
        const uint2 hv = reinterpret_cast<const uint2*>(g_Yfbh + (size_t)g_fbslot[t] * DD)[i];
        float2 a0 = __half22float2(*reinterpret_cast<const __half2*>(&hv.x));
        float2 a1 = __half22float2(*reinterpret_cast<const __half2*>(&hv.y));
        float4 v; v.x = a0.x; v.y = a0.y; v.z = a1.x; v.w = a1.y;
        o[i] = v;
    } else {
        int e0 = g_top2e[2*t], e1 = g_top2e[2*t+1];
        float w0 = g_top2w[2*t], w1 = g_top2w[2*t+1];
        size_t r0 = (size_t)(e0 * CAPACITY + g_slot[2*t]) * DD;
        size_t r1 = (size_t)(e1 * CAPACITY + g_slot[2*t+1]) * DD;
        uint2 av = reinterpret_cast<const uint2*>(g_Yeh + r0)[i];
        uint2 bv = reinterpret_cast<const uint2*>(g_Yeh + r1)[i];
        float2 a0 = __half22float2(*reinterpret_cast<const __half2*>(&av.x));
        float2 a1 = __half22float2(*reinterpret_cast<const __half2*>(&av.y));
        float2 b0 = __half22float2(*reinterpret_cast<const __half2*>(&bv.x));
        float2 b1 = __half22float2(*reinterpret_cast<const __half2*>(&bv.y));
        float4 v;
        v.x = w0 * a0.x + w1 * b0.x;
        v.y = w0 * a0.y + w1 * b0.y;
        v.z = w0 * a1.x + w1 * b1.x;
        v.w = w0 * a1.y + w1 * b1.y;
        o[i] = v;
    }
}

// ---------------- host: tensormap encode via driver entry point ----------------
typedef CUresult (*PFN_tmEncode)(CUtensorMap*, CUtensorMapDataType, cuuint32_t, void*,
                                 const cuuint64_t*, const cuuint64_t*, const cuuint32_t*,
                                 const cuuint32_t*, CUtensorMapInterleave, CUtensorMapSwizzle,
                                 CUtensorMapL2promotion, CUtensorMapFloatOOBfill);

static bool encode_tm2d(PFN_tmEncode enc, CUtensorMap* tm, void* ptr,
                        uint64_t inner, uint64_t rows, uint32_t boxrows) {
    cuuint64_t dims[2]    = {inner, rows};
    cuuint64_t strides[1] = {inner * 2};
    cuuint32_t box[2]     = {64, boxrows};
    cuuint32_t es[2]      = {1, 1};
    CUresult r = enc(tm, CU_TENSOR_MAP_DATA_TYPE_FLOAT16, 2, ptr, dims, strides, box, es,
                     CU_TENSOR_MAP_INTERLEAVE_NONE, CU_TENSOR_MAP_SWIZZLE_128B,
                     CU_TENSOR_MAP_L2_PROMOTION_L2_128B, CU_TENSOR_MAP_FLOAT_OOB_FILL_NONE);
    return r == CUDA_SUCCESS;
}

// ---------------- launch ----------------
extern "C" void kernel_launch(void* const* d_in, const int* in_sizes, int n_in,
                              void* d_out, int out_size) {
    const float* x   = (const float*)d_in[0];
    const float* Wr  = (const float*)d_in[1];
    const float* W1  = (const float*)d_in[2];
    const float* b1  = (const float*)d_in[3];
    const float* W2  = (const float*)d_in[4];
    const float* b2  = (const float*)d_in[5];
    const float* fw1 = (const float*)d_in[6];
    const float* fb1 = (const float*)d_in[7];
    const float* fw2 = (const float*)d_in[8];
    const float* fb2 = (const float*)d_in[9];
    float* out = (float*)d_out;

    __half *dW1, *dW2, *dfw1, *dfw2, *dXg, *dXfb, *dH, *dHfb;
    cudaGetSymbolAddress((void**)&dW1,  g_W1f);
    cudaGetSymbolAddress((void**)&dW2,  g_W2f);
    cudaGetSymbolAddress((void**)&dfw1, g_fw1f);
    cudaGetSymbolAddress((void**)&dfw2, g_fw2f);
    cudaGetSymbolAddress((void**)&dXg,  g_Xg);
    cudaGetSymbolAddress((void**)&dXfb, g_Xfb);
    cudaGetSymbolAddress((void**)&dH,   g_H);
    cudaGetSymbolAddress((void**)&dHfb, g_Hfb);

    cudaFuncAttributes fa{};
    cudaFuncGetAttributes(&fa, (const void*)gemm_tc5<1>);
    bool use_tc = (fa.numRegs >= 24);

    CUtensorMap tmXg{}, tmXfb{}, tmW1{}, tmFw1{}, tmH{}, tmHfb{}, tmW2{}, tmFw2{};
    if (use_tc) {
        void* fn = nullptr;
        cudaDriverEntryPointQueryResult qr;
        cudaGetDriverEntryPoint("cuTensorMapEncodeTiled", &fn, cudaEnableDefault, &qr);
        if (fn == nullptr) {
            use_tc = false;
        } else {
            PFN_tmEncode enc = (PFN_tmEncode)fn;
            bool ok = true;
            ok &= encode_tm2d(enc, &tmXg,  dXg,  DD, RR, 128);
            ok &= encode_tm2d(enc, &tmXfb, dXfb, DD, TT, 128);
            ok &= encode_tm2d(enc, &tmW1,  dW1,  DD, (uint64_t)II*EE, 256);
            ok &= encode_tm2d(enc, &tmFw1, dfw1, DD, II, 256);
            ok &= encode_tm2d(enc, &tmH,   dH,   II, RR, 128);
            ok &= encode_tm2d(enc, &tmHfb, dHfb, II, TT, 128);
            ok &= encode_tm2d(enc, &tmW2,  dW2,  II, (uint64_t)DD*EE, 256);
            ok &= encode_tm2d(enc, &tmFw2, dfw2, II, DD, 256);
            if (!ok) use_tc = false;
        }
    }

    if (use_tc) {
        cudaFuncSetAttribute(gemm_tc5<1>, cudaFuncAttributeMaxDynamicSharedMemorySize, TC_SMEM);
        cudaFuncSetAttribute(gemm_tc5<2>, cudaFuncAttributeMaxDynamicSharedMemorySize, TC_SMEM);
        router_kernel<<<TT/8, 256>>>(x, Wr);                               // 0
        assign_kernel<<<1, 1024>>>();                                      // 1
        megaprep<<<MP_TOTAL, 256>>>(x, W1, W2, fw1, fw2);                  // 2

        cudaLaunchAttribute attrs[1];
        attrs[0].id = cudaLaunchAttributeClusterDimension;
        attrs[0].val.clusterDim = {1, 2, 1};
        cudaLaunchConfig_t cfg{};
        cfg.blockDim = {256, 1, 1};
        cfg.dynamicSmemBytes = TC_SMEM;
        cfg.stream = 0;
        cfg.attrs = attrs;
        cfg.numAttrs = 1;

        cfg.gridDim = {II/TCBN, TT/TCBM, EE+1};
        cudaLaunchKernelEx(&cfg, gemm_tc5<1>, tmXg, tmXfb, tmW1, tmFw1, b1, fb1); // 3
        cfg.gridDim = {DD/TCBN, TT/TCBM, EE+1};
        cudaLaunchKernelEx(&cfg, gemm_tc5<2>, tmH, tmHfb, tmW2, tmFw2, b2, fb2);  // 4

        combine_kernel<<<TT, 256>>>(out);                                  // 5
    } else {
        cudaFuncSetAttribute(gemm_hmma<0>, cudaFuncAttributeMaxDynamicSharedMemorySize, HM_SMEM);
        cudaFuncSetAttribute(gemm_hmma<1>, cudaFuncAttributeMaxDynamicSharedMemorySize, HM_SMEM);
        cudaFuncSetAttribute(gemm_hmma<2>, cudaFuncAttributeMaxDynamicSharedMemorySize, HM_SMEM);
        cudaFuncSetAttribute(gemm_hmma<3>, cudaFuncAttributeMaxDynamicSharedMemorySize, HM_SMEM);
        router_kernel<<<TT/8, 256>>>(x, Wr);
        convert_kernel<<<(EE*DD*II/8 + 255)/256, 256>>>(W1, dW1, EE*DD*II/8);
        convert_kernel<<<(EE*II*DD/8 + 255)/256, 256>>>(W2, dW2, EE*II*DD/8);
        assign_kernel<<<1, 1024>>>();
        gather_all<<<RR + TT, 256>>>(x);
        gemm_hmma<0><<<dim3(II/BN, CAPACITY/BM, EE), 256, HM_SMEM>>>(b1);
        gemm_hmma<2><<<dim3(DD/BN, CAPACITY/BM, EE), 256, HM_SMEM>>>(b2);
        convert_kernel<<<(DD*II/8 + 255)/256, 256>>>(fw1, dfw1, DD*II/8);
        gemm_hmma<1><<<dim3(II/BN, TT/BM, 1), 256, HM_SMEM>>>(fb1);
        convert_kernel<<<(II*DD/8 + 255)/256, 256>>>(fw2, dfw2, II*DD/8);
        gemm_hmma<3><<<dim3(DD/BN, TT/BM, 1), 256, HM_SMEM>>>(fb2);
    }

    combine_kernel<<<TT, 256>>>(out);
}

// round 17
// speedup vs baseline: 1.1423x; 1.1423x over previous
#include <cuda_runtime.h>
#include <cuda.h>
#include <cuda_fp16.h>
#include <cstdint>

// ---------------- problem constants ----------------
#define TT   8192
#define DD   1024
#define II   4096
#define EE   8
#define CAPACITY 2560
#define RR   (EE*CAPACITY)

// arch-specific (sm_103a/sm_100a) feature gate for tcgen05
#if defined(__CUDA_ARCH__) && (defined(__CUDA_ARCH_FEAT_SM103_ALL) || defined(__CUDA_ARCH_FEAT_SM100_ALL) || defined(__CUDA_ARCH_SPECIFIC__) || defined(__CUDA_ARCH_FAMILY_SPECIFIC__))
#define TC_PATH 1
#else
#define TC_PATH 0
#endif

// ---------------- device scratch ----------------
__device__ __half g_W1f[(size_t)EE*DD*II];
__device__ __half g_W2f[(size_t)EE*II*DD];
__device__ __half g_fw1f[(size_t)DD*II];
__device__ __half g_fw2f[(size_t)II*DD];
__device__ __half g_Xg [(size_t)RR*DD];
__device__ __half g_Xfb[(size_t)TT*DD];
__device__ __half g_H  [(size_t)RR*II];
__device__ __half g_Hfb[(size_t)TT*II];
__device__ __half g_Yeh [(size_t)RR*DD];
__device__ __half g_Yfbh[(size_t)TT*DD];
__device__ int    g_top2e[TT*2];
__device__ float  g_top2w[TT*2];
__device__ int    g_slot [TT*2];
__device__ int    g_fbslot[TT];
__device__ int    g_fbidx [TT];
__device__ unsigned char g_fbflag[TT];
__device__ int    g_counts[EE];
__device__ int    g_fbcount;
__device__ int    g_idx[RR];
// active m-tile list (built in assign_kernel): z in [0,EE] (EE = fallback)
__device__ int    g_tile_z[256];
__device__ int    g_tile_m[256];
__device__ int    g_ntiles;

// ---------------- generic helpers ----------------
__device__ __forceinline__ float gelu_exact(float v) {
    return 0.5f * v * (1.0f + erff(v * 0.7071067811865475f));
}
__device__ __forceinline__ void cpasync16(uint32_t dst, const void* src) {
    asm volatile("cp.async.cg.shared.global [%0], [%1], 16;\n" :: "r"(dst), "l"(src));
}
__device__ __forceinline__ void cpasync_commit() { asm volatile("cp.async.commit_group;\n"); }
__device__ __forceinline__ void cpasync_wait0() { asm volatile("cp.async.wait_group 0;\n"); }
__device__ __forceinline__ void cpasync_wait1() { asm volatile("cp.async.wait_group 1;\n"); }

__device__ __forceinline__ uint32_t smem_u32(const void* p) {
    uint32_t a;
    asm("{ .reg .u64 t; cvta.to.shared.u64 t, %1; cvt.u32.u64 %0, t; }" : "=r"(a) : "l"(p));
    return a;
}
__device__ __forceinline__ void ldmatrix_x4(uint32_t* r, uint32_t addr) {
    asm volatile("ldmatrix.sync.aligned.m8n8.x4.shared.b16 {%0,%1,%2,%3}, [%4];"
                 : "=r"(r[0]), "=r"(r[1]), "=r"(r[2]), "=r"(r[3]) : "r"(addr));
}
__device__ __forceinline__ void ldmatrix_x4_trans(uint32_t* r, uint32_t addr) {
    asm volatile("ldmatrix.sync.aligned.m8n8.x4.trans.shared.b16 {%0,%1,%2,%3}, [%4];"
                 : "=r"(r[0]), "=r"(r[1]), "=r"(r[2]), "=r"(r[3]) : "r"(addr));
}
__device__ __forceinline__ void mma16816(float* c, const uint32_t* a, const uint32_t* b) {
    asm volatile("mma.sync.aligned.m16n8k16.row.col.f32.f16.f16.f32 "
                 "{%0,%1,%2,%3},{%4,%5,%6,%7},{%8,%9},{%0,%1,%2,%3};"
                 : "+f"(c[0]), "+f"(c[1]), "+f"(c[2]), "+f"(c[3])
                 : "r"(a[0]), "r"(a[1]), "r"(a[2]), "r"(a[3]), "r"(b[0]), "r"(b[1]));
}

// ---------------- mbarrier helpers ----------------
__device__ __forceinline__ void mbar_init(uint32_t a, uint32_t cnt) {
    asm volatile("mbarrier.init.shared.b64 [%0], %1;" :: "r"(a), "r"(cnt) : "memory");
}
__device__ __forceinline__ void mbar_arrive(uint32_t a) {
    asm volatile("mbarrier.arrive.shared.b64 _, [%0];" :: "r"(a) : "memory");
}
__device__ __forceinline__ void mbar_expect_tx(uint32_t a, uint32_t bytes) {
    asm volatile("mbarrier.arrive.expect_tx.shared.b64 _, [%0], %1;" :: "r"(a), "r"(bytes) : "memory");
}
__device__ __forceinline__ void mbar_wait(uint32_t a, uint32_t parity) {
    asm volatile(
        "{\n\t"
        ".reg .pred P1;\n\t"
        "WAIT_LOOP_%=:\n\t"
        "mbarrier.try_wait.parity.acquire.cta.shared::cta.b64 P1, [%0], %1, 0x989680;\n\t"
        "@P1 bra.uni WAIT_DONE_%=;\n\t"
        "bra.uni WAIT_LOOP_%=;\n\t"
        "WAIT_DONE_%=:\n\t"
        "}"
        :: "r"(a), "r"(parity) : "memory");
}
__device__ __forceinline__ void fence_proxy_async_shared() {
    asm volatile("fence.proxy.async.shared::cta;" ::: "memory");
}
// 2D TMA load global->shared::cta, mbarrier complete_tx
__device__ __forceinline__ void tma2d(uint32_t smemaddr, const CUtensorMap* tm,
                                      int cx, int cy, uint32_t mbar) {
    asm volatile("cp.async.bulk.tensor.2d.shared::cta.global.tile.mbarrier::complete_tx::bytes "
                 "[%0], [%1, {%2, %3}], [%4];"
                 :: "r"(smemaddr), "l"(tm), "r"(cx), "r"(cy), "r"(mbar) : "memory");
}

// ---------------- fp32 -> fp16 plain convert (HMMA layout [K,N]) ----------------
__global__ void convert_kernel(const float* __restrict__ src, __half* __restrict__ dst, int n8) {
    int i = blockIdx.x * blockDim.x + threadIdx.x;
    if (i < n8) {
        float4 a = reinterpret_cast<const float4*>(src)[2*i];
        float4 b = reinterpret_cast<const float4*>(src)[2*i+1];
        union { __half2 h[4]; uint4 u; } o;
        o.h[0] = __floats2half2_rn(a.x, a.y);
        o.h[1] = __floats2half2_rn(a.z, a.w);
        o.h[2] = __floats2half2_rn(b.x, b.y);
        o.h[3] = __floats2half2_rn(b.z, b.w);
        reinterpret_cast<uint4*>(dst)[i] = o.u;
    }
}

// ---------------- transpose-convert tile body (TC layout [N,K]) ----------------
__device__ __forceinline__ void tconv_tile(const float* __restrict__ src, __half* __restrict__ dst,
                                           int Kdim, int Ndim, int kb, int nb,
                                           float (*tile)[65], int tid) {
    #pragma unroll
    for (int p = 0; p < 4; p++) {
        int i = p * 256 + tid;
        int r = i >> 4, c4 = i & 15;
        float4 v = *reinterpret_cast<const float4*>(src + (size_t)(kb + r) * Ndim + nb + c4 * 4);
        tile[r][c4*4+0] = v.x; tile[r][c4*4+1] = v.y;
        tile[r][c4*4+2] = v.z; tile[r][c4*4+3] = v.w;
    }
    __syncthreads();
    #pragma unroll
    for (int p = 0; p < 2; p++) {
        int i = p * 256 + tid;
        int r = i >> 3, c = i & 7;
        union { __half2 h[4]; uint4 u; } o;
        #pragma unroll
        for (int j = 0; j < 4; j++)
            o.h[j] = __floats2half2_rn(tile[c*8 + 2*j][r], tile[c*8 + 2*j + 1][r]);
        *reinterpret_cast<uint4*>(dst + (size_t)(nb + r) * Kdim + kb + c * 8) = o.u;
    }
}

// ---------------- router ----------------
__global__ void router_kernel(const float* __restrict__ x, const float* __restrict__ Wr) {
    __shared__ float sWr[EE*DD];
    int tid = threadIdx.x;
    for (int i = tid; i < EE*DD; i += 256) sWr[i] = Wr[i];
    __syncthreads();
    int w = tid >> 5, lane = tid & 31;
    int t = blockIdx.x * 8 + w;
    const float* xr = x + (size_t)t * DD;
    float acc[EE];
    #pragma unroll
    for (int e = 0; e < EE; e++) acc[e] = 0.f;
    for (int d = lane; d < DD; d += 32) {
        float xv = xr[d];
        #pragma unroll
        for (int e = 0; e < EE; e++) acc[e] += xv * sWr[e*DD + d];
    }
    #pragma unroll
    for (int e = 0; e < EE; e++)
        #pragma unroll
        for (int o = 16; o > 0; o >>= 1) acc[e] += __shfl_xor_sync(0xffffffffu, acc[e], o);
    if (lane == 0) {
        float m = acc[0];
        #pragma unroll
        for (int e = 1; e < EE; e++) m = fmaxf(m, acc[e]);
        float p[EE], s = 0.f;
        #pragma unroll
        for (int e = 0; e < EE; e++) { p[e] = expf(acc[e] - m); s += p[e]; }
        #pragma unroll
        for (int e = 0; e < EE; e++) p[e] /= s;
        int i1 = 0;
        #pragma unroll
        for (int e = 1; e < EE; e++) if (p[e] > p[i1]) i1 = e;
        int i2 = -1;
        #pragma unroll
        for (int e = 0; e < EE; e++) if (e != i1 && (i2 < 0 || p[e] > p[i2])) i2 = e;
        float ssum = p[i1] + p[i2];
        if (ssum < 1e-9f) ssum = 1e-9f;
        g_top2e[2*t] = i1; g_top2e[2*t+1] = i2;
        g_top2w[2*t] = p[i1] / ssum; g_top2w[2*t+1] = p[i2] / ssum;
    }
}

// ---------------- sequential capacity assignment + tile-list build ----------------
__global__ void assign_kernel() {
    int tid = threadIdx.x, lane = tid & 31, wid = tid >> 5;
    __shared__ int wsum[32];
    int e0[8], e1[8];
    bool fb[8];
    #pragma unroll
    for (int i = 0; i < 8; i++) {
        int t = tid * 8 + i;
        e0[i] = g_top2e[2*t]; e1[i] = g_top2e[2*t+1];
        fb[i] = false;
    }
    for (int e = 0; e < EE; e++) {
        bool elig[8]; int cnt = 0;
        #pragma unroll
        for (int i = 0; i < 8; i++) {
            elig[i] = (!fb[i]) && (e0[i] == e || e1[i] == e);
            cnt += elig[i] ? 1 : 0;
        }
        int inc = cnt;
        #pragma unroll
        for (int o = 1; o < 32; o <<= 1) { int v = __shfl_up_sync(0xffffffffu, inc, o); if (lane >= o) inc += v; }
        if (lane == 31) wsum[wid] = inc;
        __syncthreads();
        if (wid == 0) {
            int v = wsum[lane];
            int inc2 = v;
            #pragma unroll
            for (int o = 1; o < 32; o <<= 1) { int u = __shfl_up_sync(0xffffffffu, inc2, o); if (lane >= o) inc2 += u; }
            wsum[lane] = inc2;
        }
        __syncthreads();
        int pos = inc - cnt + (wid ? wsum[wid-1] : 0);
        int total = wsum[31];
        if (tid == 0) g_counts[e] = (total < CAPACITY) ? total : CAPACITY;
        #pragma unroll
        for (int i = 0; i < 8; i++) {
            if (elig[i]) {
                int t = tid * 8 + i;
                if (pos < CAPACITY) {
                    int k = (e0[i] == e) ? 0 : 1;
                    g_slot[2*t + k] = pos;
                    g_idx[e*CAPACITY + pos] = t;
                } else {
                    fb[i] = true;
                }
                pos++;
            }
        }
        __syncthreads();
    }
    int cnt = 0;
    #pragma unroll
    for (int i = 0; i < 8; i++) cnt += fb[i] ? 1 : 0;
    int inc = cnt;
    #pragma unroll
    for (int o = 1; o < 32; o <<= 1) { int v = __shfl_up_sync(0xffffffffu, inc, o); if (lane >= o) inc += v; }
    if (lane == 31) wsum[wid] = inc;
    __syncthreads();
    if (wid == 0) {
        int v = wsum[lane];
        int inc2 = v;
        #pragma unroll
        for (int o = 1; o < 32; o <<= 1) { int u = __shfl_up_sync(0xffffffffu, inc2, o); if (lane >= o) inc2 += u; }
        wsum[lane] = inc2;
    }
    __syncthreads();
    int pos = inc - cnt + (wid ? wsum[wid-1] : 0);
    #pragma unroll
    for (int i = 0; i < 8; i++) {
        int t = tid * 8 + i;
        g_fbflag[t] = fb[i] ? 1 : 0;
        if (fb[i]) { g_fbidx[pos] = t; g_fbslot[t] = pos; pos++; }
    }
    if (tid == 0) g_fbcount = wsum[31];
    __syncthreads();
    // build the active m-tile list for the persistent GEMMs
    if (tid == 0) {
        int nt = 0;
        for (int z = 0; z < EE; z++) {
            int mt = (g_counts[z] + 127) >> 7;
            for (int m = 0; m < mt; m++) { g_tile_z[nt] = z; g_tile_m[nt] = m; nt++; }
        }
        int mtf = (g_fbcount + 127) >> 7;
        for (int m = 0; m < mtf; m++) { g_tile_z[nt] = EE; g_tile_m[nt] = m; nt++; }
        g_ntiles = nt;
    }
}

// ---------------- gather body ----------------
__device__ __forceinline__ void gather_body(const float* __restrict__ x, int r, int i) {
    int t;
    __half* dstrow;
    if (r < RR) {
        int e = r / CAPACITY;
        if (r - e*CAPACITY >= g_counts[e]) return;
        t = g_idx[r];
        dstrow = g_Xg + (size_t)r * DD;
    } else {
        int rr = r - RR;
        if (rr >= g_fbcount) return;
        t = g_fbidx[rr];
        dstrow = g_Xfb + (size_t)rr * DD;
    }
    const float4* src = reinterpret_cast<const float4*>(x + (size_t)t * DD);
    __half2* dst = reinterpret_cast<__half2*>(dstrow);
    float4 v = src[i];
    dst[2*i]   = __floats2half2_rn(v.x, v.y);
    dst[2*i+1] = __floats2half2_rn(v.z, v.w);
}

__global__ void gather_all(const float* __restrict__ x) {
    gather_body(x, blockIdx.x, threadIdx.x);
}

// ---------------- mega-prep ----------------
#define MP_GATHER (RR + TT)
#define MP_W1     (16*64*EE)
#define MP_W2     (64*16*EE)
#define MP_FW1    (16*64)
#define MP_FW2    (64*16)
#define MP_TOTAL  (MP_GATHER + MP_W1 + MP_W2 + MP_FW1 + MP_FW2)

__global__ void megaprep(const float* __restrict__ x,
                         const float* __restrict__ W1, const float* __restrict__ W2,
                         const float* __restrict__ fw1, const float* __restrict__ fw2) {
    __shared__ float tile[64][65];
    int b = blockIdx.x, tid = threadIdx.x;
    if (b < MP_GATHER) { gather_body(x, b, tid); return; }
    b -= MP_GATHER;
    if (b < MP_W1) {
        int kb = (b & 15) * 64;
        int t2 = b >> 4;
        int nb = (t2 & 63) * 64;
        int z  = t2 >> 6;
        tconv_tile(W1 + (size_t)z*DD*II, g_W1f + (size_t)z*DD*II, DD, II, kb, nb, tile, tid);
        return;
    }
    b -= MP_W1;
    if (b < MP_W2) {
        int kb = (b & 63) * 64;
        int t2 = b >> 6;
        int nb = (t2 & 15) * 64;
        int z  = t2 >> 4;
        tconv_tile(W2 + (size_t)z*II*DD, g_W2f + (size_t)z*II*DD, II, DD, kb, nb, tile, tid);
        return;
    }
    b -= MP_W2;
    if (b < MP_FW1) {
        int kb = (b & 15) * 64;
        int nb = (b >> 4) * 64;
        tconv_tile(fw1, g_fw1f, DD, II, kb, nb, tile, tid);
        return;
    }
    b -= MP_FW1;
    {
        int kb = (b & 63) * 64;
        int nb = (b >> 6) * 64;
        tconv_tile(fw2, g_fw2f, II, DD, kb, nb, tile, tid);
    }
}

// ============================================================================
// Path A: PERSISTENT tcgen05 GEMM. Grid=148, 1 CTA/SM, 320 threads.
// TMEM 512 cols = two 256-col accumulators: MMA on buf (j+1)&1 overlaps the
// epilogue of buf j&1. Warps 0-7 epilogue; warp 8 MMA issuer; warp 9 TMA.
// ============================================================================
#define TCBM 128
#define TCBN 256
#define BKH 64
#define NSTG 4
#define TC_A1 16384
#define TC_STGB 49152
#define SM_TILE0 1024
#define TC_SMEM (SM_TILE0 + NSTG*TC_STGB)   // 197632, 1 CTA/SM
#define NPERSIST 148

#define IDESC_F16_128x256 ((1u<<4) | (32u<<17) | (8u<<24))

#if TC_PATH
static __device__ __forceinline__ uint64_t make_desc(uint32_t addr) {
    const uint64_t base =
        (uint64_t(2)  << 61) | (uint64_t(1) << 46) | (uint64_t(64) << 32) | (uint64_t(1) << 16);
    return base | ((uint64_t)(addr >> 4) & 0x3FFF);
}
__device__ __forceinline__ void mma_f16_ss(uint32_t d_tmem, uint64_t adesc, uint64_t bdesc,
                                           uint32_t idesc, bool accum) {
    uint32_t en = accum ? 1u : 0u;
    asm volatile(
        "{\n\t"
        ".reg .pred p;\n\t"
        "setp.ne.u32 p, %5, 0;\n\t"
        "tcgen05.mma.cta_group::1.kind::f16 [%0], %1, %2, %3, {%4, %4, %4, %4}, p;\n\t"
        "}"
        :: "r"(d_tmem), "l"(adesc), "l"(bdesc), "r"(idesc), "r"(0u), "r"(en)
        : "memory");
}
#define TC_LD32(r, addr) \
    asm volatile( \
        "tcgen05.ld.sync.aligned.32x32b.x32.b32 " \
        "{%0, %1, %2, %3, %4, %5, %6, %7, " \
        " %8, %9, %10, %11, %12, %13, %14, %15, " \
        " %16, %17, %18, %19, %20, %21, %22, %23, " \
        " %24, %25, %26, %27, %28, %29, %30, %31}, [%32];" \
        : "=r"((r)[0]),  "=r"((r)[1]),  "=r"((r)[2]),  "=r"((r)[3]), \
          "=r"((r)[4]),  "=r"((r)[5]),  "=r"((r)[6]),  "=r"((r)[7]), \
          "=r"((r)[8]),  "=r"((r)[9]),  "=r"((r)[10]), "=r"((r)[11]), \
          "=r"((r)[12]), "=r"((r)[13]), "=r"((r)[14]), "=r"((r)[15]), \
          "=r"((r)[16]), "=r"((r)[17]), "=r"((r)[18]), "=r"((r)[19]), \
          "=r"((r)[20]), "=r"((r)[21]), "=r"((r)[22]), "=r"((r)[23]), \
          "=r"((r)[24]), "=r"((r)[25]), "=r"((r)[26]), "=r"((r)[27]), \
          "=r"((r)[28]), "=r"((r)[29]), "=r"((r)[30]), "=r"((r)[31]) \
        : "r"(addr))
#endif

template<int PHASE>
__global__ void __launch_bounds__(320, 1) gemm_tc5(
    const __grid_constant__ CUtensorMap tmAe,
    const __grid_constant__ CUtensorMap tmAf,
    const __grid_constant__ CUtensorMap tmBe,
    const __grid_constant__ CUtensorMap tmBf,
    const float* __restrict__ bias_e,
    const float* __restrict__ bias_f) {
#if TC_PATH
    constexpr bool G1 = (PHASE == 1);
    constexpr int N = G1 ? II : DD;
    constexpr int KT = (G1 ? DD : II) / BKH;    // chunks per tile (16 / 64)
    constexpr int NXT = N / TCBN;               // n-tiles (16 / 4)

    const int bid = blockIdx.x;
    const int tid = threadIdx.x, lane = tid & 31, wid = tid >> 5;
    const int ntiles = g_ntiles;
    const int ntot = ntiles * NXT;

    extern __shared__ char smem[];
    const uint32_t sb = smem_u32(smem);

    // smem map: [0] tmem ptr; full[4]@64, empty[4]@96, acc_full[2]@128, epi_done[2]@144
    const uint32_t mb_full0 = sb + 64, mb_empty0 = sb + 96;
    const uint32_t mb_accf0 = sb + 128, mb_epid0 = sb + 144;
    if (tid == 0) {
        #pragma unroll
        for (int s = 0; s < NSTG; s++) {
            mbar_init(mb_full0 + 8*s, 1);
            mbar_init(mb_empty0 + 8*s, 1);
        }
        mbar_init(mb_accf0, 1);  mbar_init(mb_accf0 + 8, 1);
        mbar_init(mb_epid0, 8);  mbar_init(mb_epid0 + 8, 8);
    }
    if (wid == 0) {
        asm volatile("tcgen05.alloc.cta_group::1.sync.aligned.shared::cta.b32 [%0], %1;"
                     :: "r"(sb), "r"(512) : "memory");
        asm volatile("tcgen05.relinquish_alloc_permit.cta_group::1.sync.aligned;");
    }
    __syncthreads();
    uint32_t tb;
    asm volatile("ld.shared.b32 %0, [%1];" : "=r"(tb) : "r"(sb));

    if (wid == 8) {
        if (lane == 0) {
            // ---- MMA issuer: all tiles, double-buffered accumulators ----
            uint64_t ad[NSTG], bd[NSTG];
            #pragma unroll
            for (int s = 0; s < NSTG; s++) {
                uint32_t base = sb + SM_TILE0 + s*TC_STGB;
                ad[s] = make_desc(base);
                bd[s] = make_desc(base + TC_A1);
            }
            uint32_t c = 0;
            int jj = 0;
            #pragma unroll 1
            for (int i = bid; i < ntot; i += NPERSIST, jj++) {
                const int buf = jj & 1;
                const uint32_t u = (uint32_t)(jj >> 1);
                mbar_wait(mb_epid0 + 8*buf, (u & 1) ^ 1u);   // buffer free?
                const uint32_t dtm = tb + (uint32_t)buf * 256;
                #pragma unroll 1
                for (int kc = 0; kc < KT; kc++) {
                    int st = c & 3;
                    uint32_t ph = (c >> 2) & 1;
                    mbar_wait(mb_full0 + 8*st, ph);
                    asm volatile("tcgen05.fence::after_thread_sync;" ::: "memory");
                    #pragma unroll
                    for (int k = 0; k < 4; k++)
                        mma_f16_ss(dtm, ad[st] + k*2, bd[st] + k*2, IDESC_F16_128x256,
                                   (kc > 0) || (k > 0));
                    asm volatile("tcgen05.commit.cta_group::1.mbarrier::arrive::one.shared::cluster.b64 [%0];"
                                 :: "r"(mb_empty0 + 8*st) : "memory");
                    c++;
                }
                asm volatile("tcgen05.commit.cta_group::1.mbarrier::arrive::one.shared::cluster.b64 [%0];"
                             :: "r"(mb_accf0 + 8*buf) : "memory");
            }
        }
    } else if (wid == 9) {
        if (lane == 0) {
            // ---- TMA producer: continuous pipeline across tiles ----
            uint32_t c = 0;
            #pragma unroll 1
            for (int i = bid; i < ntot; i += NPERSIST) {
                const int mi = i / NXT, nx = i - mi * NXT;
                const int zz = g_tile_z[mi];
                const bool FB = (zz == EE);
                const int m0 = g_tile_m[mi] * TCBM;
                const int n0 = nx * TCBN;
                const CUtensorMap* tmA = FB ? &tmAf : &tmAe;
                const CUtensorMap* tmB = FB ? &tmBf : &tmBe;
                const int rowA = FB ? m0 : zz*CAPACITY + m0;
                const int rowB = FB ? n0 : zz*N + n0;
                #pragma unroll 1
                for (int kc = 0; kc < KT; kc++) {
                    int st = c & 3;
                    uint32_t eph = ((c >> 2) & 1) ^ 1u;
                    mbar_wait(mb_empty0 + 8*st, eph);
                    uint32_t stgB = sb + SM_TILE0 + st*TC_STGB;
                    uint32_t fullb = mb_full0 + 8*st;
                    mbar_expect_tx(fullb, (uint32_t)TC_STGB);
                    tma2d(stgB,         tmA, kc*BKH, rowA, fullb);
                    tma2d(stgB + TC_A1, tmB, kc*BKH, rowB, fullb);
                    c++;
                }
            }
        }
    } else {
        // ---- epilogue: warps 0-7 ----
        const int ch = wid >> 2;          // column half
        const int lw = wid & 3;           // subpartition
        const uint32_t cbase = (uint32_t)ch * 128;
        int jj = 0;
        #pragma unroll 1
        for (int i = bid; i < ntot; i += NPERSIST, jj++) {
            const int mi = i / NXT, nx = i - mi * NXT;
            const int zz = g_tile_z[mi];
            const bool FB = (zz == EE);
            const int m0 = g_tile_m[mi] * TCBM;
            const int n0 = nx * TCBN;
            const float* biasp = (FB ? bias_f : bias_e + (size_t)zz*N) + n0;
            const int buf = jj & 1;
            const uint32_t u = (uint32_t)(jj >> 1);
            mbar_wait(mb_accf0 + 8*buf, u & 1);
            asm volatile("tcgen05.fence::after_thread_sync;" ::: "memory");
            const uint32_t tbuf = tb + (uint32_t)buf * 256;
            const int row = m0 + lw*32 + lane;
            __half* outp;
            if constexpr (G1)
                outp = (FB ? g_Hfb : g_H + (size_t)zz*CAPACITY*II) + (size_t)row * II;
            else
                outp = (FB ? g_Yfbh : g_Yeh + (size_t)zz*CAPACITY*DD) + (size_t)row * DD;
            uint32_t ra[32], rb[32];
            #pragma unroll 1
            for (int cc = 0; cc < 2; cc++) {
                TC_LD32(ra, tbuf + cbase + (2*cc)*32);
                TC_LD32(rb, tbuf + cbase + (2*cc+1)*32);
                asm volatile("tcgen05.wait::ld.sync.aligned;" ::: "memory");
                #pragma unroll
                for (int half = 0; half < 2; half++) {
                    const uint32_t* r = half ? rb : ra;
                    int cl = cbase + (2*cc + half)*32;
                    union { __half2 h[16]; uint4 uu[4]; } o;
                    #pragma unroll
                    for (int j = 0; j < 16; j++) {
                        float v0 = __uint_as_float(r[2*j])   + __ldg(biasp + cl + 2*j);
                        float v1 = __uint_as_float(r[2*j+1]) + __ldg(biasp + cl + 2*j + 1);
                        if constexpr (G1) { v0 = gelu_exact(v0); v1 = gelu_exact(v1); }
                        o.h[j] = __floats2half2_rn(v0, v1);
                    }
                    uint4* dst = reinterpret_cast<uint4*>(outp + n0 + cl);
                    dst[0] = o.uu[0]; dst[1] = o.uu[1]; dst[2] = o.uu[2]; dst[3] = o.uu[3];
                }
            }
            asm volatile("tcgen05.fence::before_thread_sync;" ::: "memory");
            if (lane == 0) mbar_arrive(mb_epid0 + 8*buf);
        }
    }

    __syncthreads();
    if (wid == 0) {
        asm volatile("tcgen05.dealloc.cta_group::1.sync.aligned.b32 %0, %1;" :: "r"(tb), "r"(512));
    }
#endif
}

// ============================================================================
// Path B: HMMA GEMM fallback ([K,N] weights), 128x128 tiles, 3-stage
// ============================================================================
#define BM 128
#define BN 128
#define HM_STGB 32768
#define HM_SMEM (3*HM_STGB)

template<int MODE>
__global__ void gemm_hmma(const float* __restrict__ bias) {
    constexpr bool G1 = (MODE < 2);
    constexpr bool FB = (MODE & 1);
    constexpr int K = G1 ? DD : II;
    constexpr int N = G1 ? II : DD;
    constexpr int KT = K / BKH;

    const int e = blockIdx.z;
    const int count = FB ? g_fbcount : g_counts[e];
    const int m0 = blockIdx.y * BM;
    if (m0 >= count) return;
    const int n0 = blockIdx.x * BN;

    const __half* __restrict__ Aexp;
    const __half* __restrict__ Bexp;
    if constexpr (MODE == 0) { Aexp = g_Xg  + (size_t)e*CAPACITY*K; Bexp = g_W1f + (size_t)e*K*II; }
    if constexpr (MODE == 1) { Aexp = g_Xfb;                        Bexp = g_fw1f; }
    if constexpr (MODE == 2) { Aexp = g_H   + (size_t)e*CAPACITY*K; Bexp = g_W2f + (size_t)e*K*DD; }
    if constexpr (MODE == 3) { Aexp = g_Hfb;                        Bexp = g_fw2f; }
    const float* biasp = bias + (FB ? 0 : (size_t)e*N);

    extern __shared__ __half smemh[];
    const uint32_t sbase = smem_u32(smemh);
    const int tid = threadIdx.x, lane = tid & 31, wid = tid >> 5;
    const int wm = wid & 1, wn = wid >> 1;
    const int g = lane >> 3, rin = lane & 7;

    float acc[4][4][4];
    #pragma unroll
    for (int a = 0; a < 4; a++)
        #pragma unroll
        for (int b = 0; b < 4; b++)
            #pragma unroll
            for (int c = 0; c < 4; c++) acc[a][b][c] = 0.f;

    auto loadStage = [&](int kt, int st) {
        if (kt < KT) {
            uint32_t aB = sbase + st * HM_STGB;
            uint32_t bB = aB + 16384;
            #pragma unroll
            for (int j = 0; j < 4; j++) {
                int id = j * 256 + tid;
                int r = id >> 3, c = id & 7;
                const __half* src = Aexp + (size_t)(m0 + r) * K + kt * BKH + c * 8;
                uint32_t dst = aB + (uint32_t)(r * 64 + ((c ^ (r & 7)) << 3)) * 2;
                cpasync16(dst, src);
            }
            #pragma unroll
            for (int j = 0; j < 4; j++) {
                int id = j * 256 + tid;
                int r = id >> 4, c = id & 15;
                const __half* src = Bexp + (size_t)(kt * BKH + r) * N + n0 + c * 8;
                uint32_t dst = bB + (uint32_t)(r * 128 + (((c & 8) | ((c ^ r) & 7)) << 3)) * 2;
                cpasync16(dst, src);
            }
        }
        cpasync_commit();
    };

    loadStage(0, 0);
    loadStage(1, 1);
    int st = 0;
    #pragma unroll 1
    for (int kt = 0; kt < KT; kt++) {
        cpasync_wait1();
        __syncthreads();
        loadStage(kt + 2, (st + 2) % 3);
        uint32_t aB = sbase + st * HM_STGB;
        uint32_t bB = aB + 16384;
        #pragma unroll
        for (int ks = 0; ks < 4; ks++) {
            uint32_t afr[4][4];
            #pragma unroll
            for (int mt = 0; mt < 4; mt++) {
                int row = wm * 64 + mt * 16 + (g & 1) * 8 + rin;
                int ch = (ks * 2 + (g >> 1)) ^ rin;
                ldmatrix_x4(afr[mt], aB + (uint32_t)(row * 64 + ch * 8) * 2);
            }
            uint32_t bfr[4][2];
            #pragma unroll
            for (int ht = 0; ht < 2; ht++) {
                int row = ks * 16 + (g & 1) * 8 + rin;
                int c = wn * 4 + ht * 2 + (g >> 1);
                int ph = (c & 8) | ((c & 7) ^ rin);
                uint32_t r4[4];
                ldmatrix_x4_trans(r4, bB + (uint32_t)(row * 128 + ph * 8) * 2);
                bfr[ht*2][0] = r4[0]; bfr[ht*2][1] = r4[1];
                bfr[ht*2+1][0] = r4[2]; bfr[ht*2+1][1] = r4[3];
            }
            #pragma unroll
            for (int mt = 0; mt < 4; mt++)
                #pragma unroll
                for (int nt = 0; nt < 4; nt++)
                    mma16816(acc[mt][nt], afr[mt], bfr[nt]);
        }
        st = (st + 1) % 3;
    }

    const int growb = m0 + wm * 64;
    const int gcolb = n0 + wn * 32;
    #pragma unroll
    for (int mt = 0; mt < 4; mt++) {
        #pragma unroll
        for (int nt = 0; nt < 4; nt++) {
            int r0 = growb + mt * 16 + (lane >> 2);
            int c0 = gcolb + nt * 8 + (lane & 3) * 2;
            float b0f = biasp[c0], b1f = biasp[c0 + 1];
            float x0 = acc[mt][nt][0] + b0f, x1 = acc[mt][nt][1] + b1f;
            float x2 = acc[mt][nt][2] + b0f, x3 = acc[mt][nt][3] + b1f;
            if constexpr (G1) {
                __half* Hout = FB ? g_Hfb : (g_H + (size_t)e*CAPACITY*N);
                *reinterpret_cast<__half2*>(Hout + (size_t)r0 * N + c0) =
                    __floats2half2_rn(gelu_exact(x0), gelu_exact(x1));
                *reinterpret_cast<__half2*>(Hout + (size_t)(r0 + 8) * N + c0) =
                    __floats2half2_rn(gelu_exact(x2), gelu_exact(x3));
            } else {
                __half* Yout = FB ? g_Yfbh : (g_Yeh + (size_t)e*CAPACITY*N);
                *reinterpret_cast<__half2*>(Yout + (size_t)r0 * N + c0) =
                    __floats2half2_rn(x0, x1);
                *reinterpret_cast<__half2*>(Yout + (size_t)(r0 + 8) * N + c0) =
                    __floats2half2_rn(x2, x3);
            }
        }
    }
}

// ---------------- final combine (fp16 expert outputs) ----------------
__global__ void combine_kernel(float* __restrict__ out) {
    int t = blockIdx.x;
    int i = threadIdx.x;
    float4* o = reinterpret_cast<float4*>(out + (size_t)t * DD);
    if (g_fbflag[t]) {
        const uint2 hv = reinterpret_cast<const uint2*>(g_Yfbh + (size_t)g_fbslot[t] * DD)[i];
        float2 a0 = __half22float2(*reinterpret_cast<const __half2*>(&hv.x));
        float2 a1 = __half22float2(*reinterpret_cast<const __half2*>(&hv.y));
        float4 v; v.x = a0.x; v.y = a0.y; v.z = a1.x; v.w = a1.y;
        o[i] = v;
    } else {
        int e0 = g_top2e[2*t], e1 = g_top2e[2*t+1];
        float w0 = g_top2w[2*t], w1 = g_top2w[2*t+1];
        size_t r0 = (size_t)(e0 * CAPACITY + g_slot[2*t]) * DD;
        size_t r1 = (size_t)(e1 * CAPACITY + g_slot[2*t+1]) * DD;
        uint2 av = reinterpret_cast<const uint2*>(g_Yeh + r0)[i];
        uint2 bv = reinterpret_cast<const uint2*>(g_Yeh + r1)[i];
        float2 a0 = __half22float2(*reinterpret_cast<const __half2*>(&av.x));
        float2 a1 = __half22float2(*reinterpret_cast<const __half2*>(&av.y));
        float2 b0 = __half22float2(*reinterpret_cast<const __half2*>(&bv.x));
        float2 b1 = __half22float2(*reinterpret_cast<const __half2*>(&bv.y));
        float4 v;
        v.x = w0 * a0.x + w1 * b0.x;
        v.y = w0 * a0.y + w1 * b0.y;
        v.z = w0 * a1.x + w1 * b1.x;
        v.w = w0 * a1.y + w1 * b1.y;
        o[i] = v;
    }
}

// ---------------- host: tensormap encode via driver entry point ----------------
typedef CUresult (*PFN_tmEncode)(CUtensorMap*, CUtensorMapDataType, cuuint32_t, void*,
                                 const cuuint64_t*, const cuuint64_t*, const cuuint32_t*,
                                 const cuuint32_t*, CUtensorMapInterleave, CUtensorMapSwizzle,
                                 CUtensorMapL2promotion, CUtensorMapFloatOOBfill);

static bool encode_tm2d(PFN_tmEncode enc, CUtensorMap* tm, void* ptr,
                        uint64_t inner, uint64_t rows, uint32_t boxrows) {
    cuuint64_t dims[2]    = {inner, rows};
    cuuint64_t strides[1] = {inner * 2};
    cuuint32_t box[2]     = {64, boxrows};
    cuuint32_t es[2]      = {1, 1};
    CUresult r = enc(tm, CU_TENSOR_MAP_DATA_TYPE_FLOAT16, 2, ptr, dims, strides, box, es,
                     CU_TENSOR_MAP_INTERLEAVE_NONE, CU_TENSOR_MAP_SWIZZLE_128B,
                     CU_TENSOR_MAP_L2_PROMOTION_L2_128B, CU_TENSOR_MAP_FLOAT_OOB_FILL_NONE);
    return r == CUDA_SUCCESS;
}

// ---------------- launch ----------------
extern "C" void kernel_launch(void* const* d_in, const int* in_sizes, int n_in,
                              void* d_out, int out_size) {
    const float* x   = (const float*)d_in[0];
    const float* Wr  = (const float*)d_in[1];
    const float* W1  = (const float*)d_in[2];
    const float* b1  = (const float*)d_in[3];
    const float* W2  = (const float*)d_in[4];
    const float* b2  = (const float*)d_in[5];
    const float* fw1 = (const float*)d_in[6];
    const float* fb1 = (const float*)d_in[7];
    const float* fw2 = (const float*)d_in[8];
    const float* fb2 = (const float*)d_in[9];
    float* out = (float*)d_out;

    __half *dW1, *dW2, *dfw1, *dfw2, *dXg, *dXfb, *dH, *dHfb;
    cudaGetSymbolAddress((void**)&dW1,  g_W1f);
    cudaGetSymbolAddress((void**)&dW2,  g_W2f);
    cudaGetSymbolAddress((void**)&dfw1, g_fw1f);
    cudaGetSymbolAddress((void**)&dfw2, g_fw2f);
    cudaGetSymbolAddress((void**)&dXg,  g_Xg);
    cudaGetSymbolAddress((void**)&dXfb, g_Xfb);
    cudaGetSymbolAddress((void**)&dH,   g_H);
    cudaGetSymbolAddress((void**)&dHfb, g_Hfb);

    cudaFuncAttributes fa{};
    cudaFuncGetAttributes(&fa, (const void*)gemm_tc5<1>);
    bool use_tc = (fa.numRegs >= 24);

    CUtensorMap tmXg{}, tmXfb{}, tmW1{}, tmFw1{}, tmH{}, tmHfb{}, tmW2{}, tmFw2{};
    if (use_tc) {
        void* fn = nullptr;
        cudaDriverEntryPointQueryResult qr;
        cudaGetDriverEntryPoint("cuTensorMapEncodeTiled", &fn, cudaEnableDefault, &qr);
        if (fn == nullptr) {
            use_tc = false;
        } else {
            PFN_tmEncode enc = (PFN_tmEncode)fn;
            bool ok = true;
            ok &= encode_tm2d(enc, &tmXg,  dXg,  DD, RR, 128);
            ok &= encode_tm2d(enc, &tmXfb, dXfb, DD, TT, 128);
            ok &= encode_tm2d(enc, &tmW1,  dW1,  DD, (uint64_t)II*EE, 256);
            ok &= encode_tm2d(enc, &tmFw1, dfw1, DD, II, 256);
            ok &= encode_tm2d(enc, &tmH,   dH,   II, RR, 128);
            ok &= encode_tm2d(enc, &tmHfb, dHfb, II, TT, 128);
            ok &= encode_tm2d(enc, &tmW2,  dW2,  II, (uint64_t)DD*EE, 256);
            ok &= encode_tm2d(enc, &tmFw2, dfw2, II, DD, 256);
            if (!ok) use_tc = false;
        }
    }

    if (use_tc) {
        cudaFuncSetAttribute(gemm_tc5<1>, cudaFuncAttributeMaxDynamicSharedMemorySize, TC_SMEM);
        cudaFuncSetAttribute(gemm_tc5<2>, cudaFuncAttributeMaxDynamicSharedMemorySize, TC_SMEM);
        router_kernel<<<TT/8, 256>>>(x, Wr);                               // 0
        assign_kernel<<<1, 1024>>>();                                      // 1
        megaprep<<<MP_TOTAL, 256>>>(x, W1, W2, fw1, fw2);                  // 2
        gemm_tc5<1><<<NPERSIST, 320, TC_SMEM>>>(tmXg, tmXfb, tmW1, tmFw1, b1, fb1); // 3
        gemm_tc5<2><<<NPERSIST, 320, TC_SMEM>>>(tmH, tmHfb, tmW2, tmFw2, b2, fb2);  // 4
        combine_kernel<<<TT, 256>>>(out);                                  // 5
    } else {
        cudaFuncSetAttribute(gemm_hmma<0>, cudaFuncAttributeMaxDynamicSharedMemorySize, HM_SMEM);
        cudaFuncSetAttribute(gemm_hmma<1>, cudaFuncAttributeMaxDynamicSharedMemorySize, HM_SMEM);
        cudaFuncSetAttribute(gemm_hmma<2>, cudaFuncAttributeMaxDynamicSharedMemorySize, HM_SMEM);
        cudaFuncSetAttribute(gemm_hmma<3>, cudaFuncAttributeMaxDynamicSharedMemorySize, HM_SMEM);
        router_kernel<<<TT/8, 256>>>(x, Wr);
        convert_kernel<<<(EE*DD*II/8 + 255)/256, 256>>>(W1, dW1, EE*DD*II/8);
        convert_kernel<<<(EE*II*DD/8 + 255)/256, 256>>>(W2, dW2, EE*II*DD/8);
        assign_kernel<<<1, 1024>>>();
        gather_all<<<RR + TT, 256>>>(x);
        gemm_hmma<0><<<dim3(II/BN, CAPACITY/BM, EE), 256, HM_SMEM>>>(b1);
        gemm_hmma<2><<<dim3(DD/BN, CAPACITY/BM, EE), 256, HM_SMEM>>>(b2);
        convert_kernel<<<(DD*II/8 + 255)/256, 256>>>(fw1, dfw1, DD*II/8);
        gemm_hmma<1><<<dim3(II/BN, TT/BM, 1), 256, HM_SMEM>>>(fb1);
        convert_kernel<<<(II*DD/8 + 255)/256, 256>>>(fw2, dfw2, II*DD/8);
        gemm_hmma<3><<<dim3(DD/BN, TT/BM, 1), 256, HM_SMEM>>>(fb2);
    }

    combine_kernel<<<TT, 256>>>(out);
}